// round 1
// baseline (speedup 1.0000x reference)
#include <cuda_runtime.h>
#include <math.h>

// Problem constants (LinearAttention_22943715295778)
#define PB 4
#define PN 8192
#define PM 2048
#define PC 512
#define PL 256
#define PH 8
#define DL 32   // L/H
#define DC 64   // C/H
#define EPS 1e-6f

// -------- device-global scratch (allocation-free requirement) --------
__device__ float g_k[PB * PN * PL];      // 32 MB : elu(X@Wk+bk)+1
__device__ float g_v[PB * PN * PC];      // 64 MB : X@Wv+bv
__device__ float g_q[PB * PM * PL];      //  8 MB : elu(Q@Wq+bq)+1
__device__ float g_acc[PB * PH * DC * DL + PB * PH * DL]; // kv (65536) + ksum (1024)

__global__ void zero_kernel(int n) {
    int i = blockIdx.x * blockDim.x + threadIdx.x;
    if (i < n) g_acc[i] = 0.0f;
}

// ---------------------------------------------------------------------
// Tiled SGEMM: out[M,N] = A[M,K] @ W[K,N] + bias, optional elu(x)+1
// BM=128, BN=64, BK=16, 256 threads, 8x4 microtile per thread.
// M % 128 == 0, N % 64 == 0, K % 16 == 0 (holds for all three launches).
// which: 0 -> g_k, 1 -> g_v, 2 -> g_q
// ---------------------------------------------------------------------
#define BM 128
#define BN 64
#define BK 16

__global__ __launch_bounds__(256) void gemm_bias_kernel(
    const float* __restrict__ A, const float* __restrict__ W,
    const float* __restrict__ bias,
    int Mrows, int Ncols, int Kdim, int elu, int which)
{
    float* __restrict__ out = (which == 0) ? g_k : (which == 1) ? g_v : g_q;

    __shared__ float As[BK][BM];
    __shared__ float Bs[BK][BN];

    const int t  = threadIdx.x;
    const int tx = t & 15;   // col group (4 cols each)
    const int ty = t >> 4;   // row group (8 rows each)
    const int row0 = blockIdx.y * BM;
    const int col0 = blockIdx.x * BN;

    float acc[8][4];
#pragma unroll
    for (int i = 0; i < 8; i++)
#pragma unroll
        for (int j = 0; j < 4; j++) acc[i][j] = 0.0f;

    for (int k0 = 0; k0 < Kdim; k0 += BK) {
        // A tile: 128x16 = 512 float4 loads, 2 per thread, stored transposed
#pragma unroll
        for (int i = 0; i < 2; i++) {
            int idx = t * 2 + i;          // 0..511
            int r   = idx >> 2;
            int c4  = idx & 3;
            float4 a = *(const float4*)&A[(size_t)(row0 + r) * Kdim + k0 + c4 * 4];
            As[c4 * 4 + 0][r] = a.x;
            As[c4 * 4 + 1][r] = a.y;
            As[c4 * 4 + 2][r] = a.z;
            As[c4 * 4 + 3][r] = a.w;
        }
        // B tile: 16x64 = 256 float4 loads, 1 per thread
        {
            int k  = t >> 4;
            int n4 = t & 15;
            *(float4*)&Bs[k][n4 * 4] =
                *(const float4*)&W[(size_t)(k0 + k) * Ncols + col0 + n4 * 4];
        }
        __syncthreads();

#pragma unroll
        for (int kk = 0; kk < BK; kk++) {
            float af[8], bf[4];
            float4 a0 = *(const float4*)&As[kk][ty * 8];
            float4 a1 = *(const float4*)&As[kk][ty * 8 + 4];
            af[0]=a0.x; af[1]=a0.y; af[2]=a0.z; af[3]=a0.w;
            af[4]=a1.x; af[5]=a1.y; af[6]=a1.z; af[7]=a1.w;
            float4 b0 = *(const float4*)&Bs[kk][tx * 4];
            bf[0]=b0.x; bf[1]=b0.y; bf[2]=b0.z; bf[3]=b0.w;
#pragma unroll
            for (int i = 0; i < 8; i++)
#pragma unroll
                for (int j = 0; j < 4; j++)
                    acc[i][j] += af[i] * bf[j];
        }
        __syncthreads();
    }

    // epilogue: bias + optional elu(x)+1, vectorized store
    float4 bvec = *(const float4*)&bias[col0 + tx * 4];
    float bf4[4] = {bvec.x, bvec.y, bvec.z, bvec.w};
#pragma unroll
    for (int i = 0; i < 8; i++) {
        int r = row0 + ty * 8 + i;
        float o[4];
#pragma unroll
        for (int j = 0; j < 4; j++) {
            float x = acc[i][j] + bf4[j];
            o[j] = elu ? (x > 0.0f ? x + 1.0f : __expf(x) * 0.0f + expf(x)) : x;
        }
        float4 st = {o[0], o[1], o[2], o[3]};
        *(float4*)&out[(size_t)r * Ncols + col0 + tx * 4] = st;
    }
}

// ---------------------------------------------------------------------
// kv[b,h,c,d] = sum_n k[b,n,h,d] * v[b,n,h,c];  ksum[b,h,d] = sum_n k
// grid = B*H*NCHUNK blocks, 256 threads. Each thread owns 8 (c,d) cells.
// ---------------------------------------------------------------------
#define NCHUNK 16

__global__ __launch_bounds__(256) void kv_accum_kernel()
{
    const int bid   = blockIdx.x;
    const int chunk = bid % NCHUNK;
    const int bh    = bid / NCHUNK;   // b*H + h
    const int h     = bh % PH;
    const int b     = bh / PH;
    const int n0    = chunk * (PN / NCHUNK);

    __shared__ float ks[64][32];
    __shared__ float vs[64][64];

    const int t  = threadIdx.x;
    const int d  = t & 31;
    const int cb = (t >> 5) * 8;

    float acc[8];
#pragma unroll
    for (int j = 0; j < 8; j++) acc[j] = 0.0f;
    float ksacc = 0.0f;

    for (int nt = 0; nt < PN / NCHUNK; nt += 64) {
#pragma unroll
        for (int i = 0; i < 8; i++) {
            int flat = t + i * 256;
            int nl = flat >> 5, dd = flat & 31;
            ks[nl][dd] = g_k[(size_t)(b * PN + n0 + nt + nl) * PL + h * DL + dd];
        }
#pragma unroll
        for (int i = 0; i < 16; i++) {
            int flat = t + i * 256;
            int nl = flat >> 6, cc = flat & 63;
            vs[nl][cc] = g_v[(size_t)(b * PN + n0 + nt + nl) * PC + h * DC + cc];
        }
        __syncthreads();
#pragma unroll 4
        for (int nl = 0; nl < 64; nl++) {
            float kval = ks[nl][d];
            ksacc += kval;
#pragma unroll
            for (int j = 0; j < 8; j++)
                acc[j] += kval * vs[nl][cb + j];
        }
        __syncthreads();
    }

    float* kv = g_acc;                       // [B*H][64][32]
    float* ksum = g_acc + PB * PH * DC * DL; // [B*H][32]
#pragma unroll
    for (int j = 0; j < 8; j++)
        atomicAdd(&kv[((size_t)bh * DC + cb + j) * DL + d], acc[j]);
    if (t < 32)
        atomicAdd(&ksum[bh * DL + t], ksacc);
}

// ---------------------------------------------------------------------
// out[b,m,h,c] = z * sum_d q[b,m,h,d] * kv[b,h,c,d]
// z = 1/(sum_d q[b,m,h,d]*ksum[b,h,d] + eps)
// grid = (B*H, M/64), 256 threads (8 warps x 8 m's each).
// ---------------------------------------------------------------------
__global__ __launch_bounds__(256) void out_kernel(const float* __restrict__ q_unused,
                                                  float* __restrict__ out)
{
    const int bh = blockIdx.x;
    const int b = bh / PH, h = bh % PH;
    const int m0 = blockIdx.y * 64;

    __shared__ float kvs[64][33];  // padded: bank = (c + d) % 32, conflict-free
    __shared__ float kss[32];

    const float* kv   = g_acc;
    const float* ksum = g_acc + PB * PH * DC * DL;

    const int t = threadIdx.x;
#pragma unroll
    for (int i = 0; i < 8; i++) {
        int flat = t + i * 256;
        int c = flat >> 5, d = flat & 31;
        kvs[c][d] = kv[(size_t)bh * (DC * DL) + flat];
    }
    if (t < 32) kss[t] = ksum[bh * DL + t];
    __syncthreads();

    const int w = t >> 5, l = t & 31;
    for (int mi = 0; mi < 8; mi++) {
        int m = m0 + w * 8 + mi;
        float qv = g_q[(size_t)(b * PM + m) * PL + h * DL + l];
        float zp = qv * kss[l];
#pragma unroll
        for (int off = 16; off; off >>= 1)
            zp += __shfl_xor_sync(0xffffffffu, zp, off);
        float z = 1.0f / (zp + EPS);

        float a0 = 0.0f, a1 = 0.0f;
#pragma unroll
        for (int dd = 0; dd < 32; dd++) {
            float qd = __shfl_sync(0xffffffffu, qv, dd);
            a0 += qd * kvs[l][dd];
            a1 += qd * kvs[l + 32][dd];
        }
        size_t o = (size_t)(b * PM + m) * PC + h * DC;
        out[o + l]      = z * a0;
        out[o + l + 32] = z * a1;
    }
}

// ---------------------------------------------------------------------
extern "C" void kernel_launch(void* const* d_in, const int* in_sizes, int n_in,
                              void* d_out, int out_size)
{
    const float* input = (const float*)d_in[0];  // [B,N,C]
    const float* query = (const float*)d_in[1];  // [B,M,C]
    const float* Wq    = (const float*)d_in[2];  // [C,L]
    const float* bq    = (const float*)d_in[3];  // [L]
    const float* Wk    = (const float*)d_in[4];  // [C,L]
    const float* bk    = (const float*)d_in[5];  // [L]
    const float* Wv    = (const float*)d_in[6];  // [C,C]
    const float* bv    = (const float*)d_in[7];  // [C]
    float* out = (float*)d_out;

    (void)in_sizes; (void)n_in; (void)out_size;

    // 1) zero kv/ksum accumulators
    int nacc = PB * PH * DC * DL + PB * PH * DL;
    zero_kernel<<<(nacc + 255) / 256, 256>>>(nacc);

    // 2) k = elu(X@Wk + bk) + 1   -> g_k   [B*N, L]
    gemm_bias_kernel<<<dim3(PL / BN, (PB * PN) / BM), 256>>>(
        input, Wk, bk, PB * PN, PL, PC, 1, 0);

    // 3) v = X@Wv + bv            -> g_v   [B*N, C]
    gemm_bias_kernel<<<dim3(PC / BN, (PB * PN) / BM), 256>>>(
        input, Wv, bv, PB * PN, PC, PC, 0, 1);

    // 4) q = elu(Q@Wq + bq) + 1   -> g_q   [B*M, L]
    gemm_bias_kernel<<<dim3(PL / BN, (PB * PM) / BM), 256>>>(
        query, Wq, bq, PB * PM, PL, PC, 1, 2);

    // 5) kv / ksum accumulation
    kv_accum_kernel<<<PB * PH * NCHUNK, 256>>>();

    // 6) output
    out_kernel<<<dim3(PB * PH, PM / 64), 256>>>(nullptr, out);
}

// round 3
// speedup vs baseline: 2.3947x; 2.3947x over previous
#include <cuda_runtime.h>
#include <cstdint>
#include <math.h>

// Problem constants (LinearAttention_22943715295778)
#define PB 4
#define PN 8192
#define PM 2048
#define PC 512
#define PL 256
#define PH 8
#define DL 32   // L/H
#define DC 64   // C/H
#define EPS 1e-6f

// -------- device-global scratch (allocation-free requirement) --------
__device__ float g_k[PB * PN * PL];      // 32 MB : elu(X@Wk+bk)+1
__device__ float g_v[PB * PN * PC];      // 64 MB : X@Wv+bv
__device__ float g_q[PB * PM * PL];      //  8 MB : elu(Q@Wq+bq)+1
__device__ float g_acc[PB * PH * DC * DL + PB * PH * DL]; // kv + ksum
__device__ float g_wt[PL * PC + PC * PC + PL * PC];       // WkT, WvT, WqT (tf32-rounded)

// ===================== helpers =====================
__device__ __forceinline__ uint32_t smem_u32(const void* p) {
    uint32_t a;
    asm("{ .reg .u64 t; cvta.to.shared.u64 t, %1; cvt.u32.u64 %0, t; }"
        : "=r"(a) : "l"(p));
    return a;
}
__device__ __forceinline__ uint32_t tf32r(float x) {  // round-to-nearest tf32
    uint32_t y;
    asm("cvt.rna.tf32.f32 %0, %1;" : "=r"(y) : "f"(x));
    return y;
}

// ===================== small kernels =====================
__global__ void zero_kernel(int n) {
    int i = blockIdx.x * blockDim.x + threadIdx.x;
    if (i < n) g_acc[i] = 0.0f;
}

// Wt[n*512 + k] = tf32(W[k*N + n]); K is always 512.
__global__ __launch_bounds__(256) void transpose_kernel(
    const float* __restrict__ W, int N, int wt_off)
{
    float* __restrict__ out = g_wt + wt_off;
    __shared__ float tile[32][33];
    int n0 = blockIdx.x * 32, k0 = blockIdx.y * 32;
    int tx = threadIdx.x, ty = threadIdx.y;
    for (int i = ty; i < 32; i += 8)
        tile[i][tx] = W[(size_t)(k0 + i) * N + n0 + tx];
    __syncthreads();
    for (int i = ty; i < 32; i += 8)
        out[(size_t)(n0 + i) * PC + k0 + tx] = __uint_as_float(tf32r(tile[tx][i]));
}

// ===================== tf32 mma.sync GEMM =====================
// out[M,N] = A[M,512] @ Wt[N,512]^T + bias  (optional elu(x)+1)
// CTA tile 128x128, BK=32, cp.async double-buffered.
// 8 warps: 4 in M x 2 in N; warp tile 32x64 via m16n8k8 (2 x 8 mma tiles).
#define TM 128
#define TN 128
#define BK 32
#define KPAD 36
#define NCH (PC / BK)   // 16
#define SMEM_BYTES (4 * (2 * TM * KPAD + 2 * TN * KPAD))  // 73728

__global__ __launch_bounds__(256, 2) void gemm_mma_kernel(
    const float* __restrict__ A, int wt_off, const float* __restrict__ bias,
    int Ncols, int elu, int which)
{
    extern __shared__ float sm[];
    float* As = sm;                     // [2][TM][KPAD]
    float* Bs = sm + 2 * TM * KPAD;     // [2][TN][KPAD]
    const float* __restrict__ Bt = g_wt + wt_off;
    float* __restrict__ out = (which == 0) ? g_k : (which == 1) ? g_v : g_q;

    const int t    = threadIdx.x;
    const int wid  = t >> 5, lane = t & 31;
    const int lr   = lane >> 2, lc = lane & 3;
    const int wm   = (wid & 3) * 32;    // warp row offset within tile
    const int wn   = (wid >> 2) * 64;   // warp col offset within tile
    const int row0 = blockIdx.y * TM;
    const int col0 = blockIdx.x * TN;

    float acc[2][8][4];
#pragma unroll
    for (int mi = 0; mi < 2; mi++)
#pragma unroll
        for (int ni = 0; ni < 8; ni++)
#pragma unroll
            for (int j = 0; j < 4; j++) acc[mi][ni][j] = 0.0f;

    // ---- async staging of one K-chunk (A:128x32, B:128x32) ----
    auto stage = [&](int c, int buf) {
        const float* Ag = A  + (size_t)row0 * PC + c * BK;
        const float* Bg = Bt + (size_t)col0 * PC + c * BK;
        float* Ad = As + buf * TM * KPAD;
        float* Bd = Bs + buf * TN * KPAD;
#pragma unroll
        for (int i = 0; i < 4; i++) {
            int idx = i * 256 + t;          // 0..1023
            int r = idx >> 3, c4 = idx & 7;
            uint32_t da = smem_u32(Ad + r * KPAD + c4 * 4);
            asm volatile("cp.async.cg.shared.global [%0], [%1], 16;"
                         :: "r"(da), "l"(Ag + (size_t)r * PC + c4 * 4));
            uint32_t db = smem_u32(Bd + r * KPAD + c4 * 4);
            asm volatile("cp.async.cg.shared.global [%0], [%1], 16;"
                         :: "r"(db), "l"(Bg + (size_t)r * PC + c4 * 4));
        }
        asm volatile("cp.async.commit_group;" ::: "memory");
    };

    auto compute = [&](int buf) {
        const float* Ab = As + buf * TM * KPAD + wm * KPAD;
        const float* Bb = Bs + buf * TN * KPAD + wn * KPAD;
#pragma unroll
        for (int kk = 0; kk < BK; kk += 8) {
            uint32_t af[2][4], bf[8][2];
#pragma unroll
            for (int mi = 0; mi < 2; mi++) {
                const float* p = Ab + mi * 16 * KPAD;
                af[mi][0] = tf32r(p[(lr    ) * KPAD + kk + lc    ]);
                af[mi][1] = tf32r(p[(lr + 8) * KPAD + kk + lc    ]);
                af[mi][2] = tf32r(p[(lr    ) * KPAD + kk + lc + 4]);
                af[mi][3] = tf32r(p[(lr + 8) * KPAD + kk + lc + 4]);
            }
#pragma unroll
            for (int ni = 0; ni < 8; ni++) {
                const float* p = Bb + ni * 8 * KPAD;
                bf[ni][0] = __float_as_uint(p[lr * KPAD + kk + lc    ]);
                bf[ni][1] = __float_as_uint(p[lr * KPAD + kk + lc + 4]);
            }
#pragma unroll
            for (int mi = 0; mi < 2; mi++)
#pragma unroll
                for (int ni = 0; ni < 8; ni++) {
                    asm volatile(
                        "mma.sync.aligned.m16n8k8.row.col.f32.tf32.tf32.f32 "
                        "{%0,%1,%2,%3}, {%4,%5,%6,%7}, {%8,%9}, {%0,%1,%2,%3};"
                        : "+f"(acc[mi][ni][0]), "+f"(acc[mi][ni][1]),
                          "+f"(acc[mi][ni][2]), "+f"(acc[mi][ni][3])
                        : "r"(af[mi][0]), "r"(af[mi][1]),
                          "r"(af[mi][2]), "r"(af[mi][3]),
                          "r"(bf[ni][0]), "r"(bf[ni][1]));
                }
        }
    };

    stage(0, 0);
    for (int c = 0; c < NCH; c++) {
        if (c + 1 < NCH) {
            stage(c + 1, (c + 1) & 1);
            asm volatile("cp.async.wait_group 1;" ::: "memory");
        } else {
            asm volatile("cp.async.wait_group 0;" ::: "memory");
        }
        __syncthreads();
        compute(c & 1);
        __syncthreads();
    }

    // ---- epilogue: bias + optional elu(x)+1, float2 stores ----
#pragma unroll
    for (int mi = 0; mi < 2; mi++) {
#pragma unroll
        for (int ni = 0; ni < 8; ni++) {
            int r0 = row0 + wm + mi * 16 + lr;
            int cc = col0 + wn + ni * 8 + 2 * lc;
            float b0 = bias[cc], b1 = bias[cc + 1];
            float x0 = acc[mi][ni][0] + b0;
            float x1 = acc[mi][ni][1] + b1;
            float x2 = acc[mi][ni][2] + b0;
            float x3 = acc[mi][ni][3] + b1;
            if (elu) {
                x0 = x0 > 0.0f ? x0 + 1.0f : expf(x0);
                x1 = x1 > 0.0f ? x1 + 1.0f : expf(x1);
                x2 = x2 > 0.0f ? x2 + 1.0f : expf(x2);
                x3 = x3 > 0.0f ? x3 + 1.0f : expf(x3);
            }
            float2 s0 = {x0, x1}, s1 = {x2, x3};
            *(float2*)&out[(size_t)r0 * Ncols + cc]       = s0;
            *(float2*)&out[(size_t)(r0 + 8) * Ncols + cc] = s1;
        }
    }
}

// ---------------------------------------------------------------------
// kv[b,h,c,d] = sum_n k[b,n,h,d] * v[b,n,h,c];  ksum[b,h,d] = sum_n k
// ---------------------------------------------------------------------
#define NCHUNK 16

__global__ __launch_bounds__(256) void kv_accum_kernel()
{
    const int bid   = blockIdx.x;
    const int chunk = bid % NCHUNK;
    const int bh    = bid / NCHUNK;
    const int h     = bh % PH;
    const int b     = bh / PH;
    const int n0    = chunk * (PN / NCHUNK);

    __shared__ float ks[64][32];
    __shared__ float vs[64][64];

    const int t  = threadIdx.x;
    const int d  = t & 31;
    const int cb = (t >> 5) * 8;

    float acc[8];
#pragma unroll
    for (int j = 0; j < 8; j++) acc[j] = 0.0f;
    float ksacc = 0.0f;

    for (int nt = 0; nt < PN / NCHUNK; nt += 64) {
#pragma unroll
        for (int i = 0; i < 8; i++) {
            int flat = t + i * 256;
            int nl = flat >> 5, dd = flat & 31;
            ks[nl][dd] = g_k[(size_t)(b * PN + n0 + nt + nl) * PL + h * DL + dd];
        }
#pragma unroll
        for (int i = 0; i < 16; i++) {
            int flat = t + i * 256;
            int nl = flat >> 6, cc = flat & 63;
            vs[nl][cc] = g_v[(size_t)(b * PN + n0 + nt + nl) * PC + h * DC + cc];
        }
        __syncthreads();
#pragma unroll 4
        for (int nl = 0; nl < 64; nl++) {
            float kval = ks[nl][d];
            ksacc += kval;
#pragma unroll
            for (int j = 0; j < 8; j++)
                acc[j] += kval * vs[nl][cb + j];
        }
        __syncthreads();
    }

    float* kv   = g_acc;
    float* ksum = g_acc + PB * PH * DC * DL;
#pragma unroll
    for (int j = 0; j < 8; j++)
        atomicAdd(&kv[((size_t)bh * DC + cb + j) * DL + d], acc[j]);
    if (t < 32)
        atomicAdd(&ksum[bh * DL + t], ksacc);
}

// ---------------------------------------------------------------------
// out[b,m,h,c] = z * sum_d q[b,m,h,d] * kv[b,h,c,d]
// ---------------------------------------------------------------------
__global__ __launch_bounds__(256) void out_kernel(float* __restrict__ out)
{
    const int bh = blockIdx.x;
    const int b = bh / PH, h = bh % PH;
    const int m0 = blockIdx.y * 64;

    __shared__ float kvs[64][33];
    __shared__ float kss[32];

    const float* kv   = g_acc;
    const float* ksum = g_acc + PB * PH * DC * DL;

    const int t = threadIdx.x;
#pragma unroll
    for (int i = 0; i < 8; i++) {
        int flat = t + i * 256;
        int c = flat >> 5, dd = flat & 31;
        kvs[c][dd] = kv[(size_t)bh * (DC * DL) + flat];
    }
    if (t < 32) kss[t] = ksum[bh * DL + t];
    __syncthreads();

    const int w = t >> 5, l = t & 31;
    for (int mi = 0; mi < 8; mi++) {
        int m = m0 + w * 8 + mi;
        float qv = g_q[(size_t)(b * PM + m) * PL + h * DL + l];
        float zp = qv * kss[l];
#pragma unroll
        for (int off = 16; off; off >>= 1)
            zp += __shfl_xor_sync(0xffffffffu, zp, off);
        float z = 1.0f / (zp + EPS);

        float a0 = 0.0f, a1 = 0.0f;
#pragma unroll
        for (int dd = 0; dd < 32; dd++) {
            float qd = __shfl_sync(0xffffffffu, qv, dd);
            a0 += qd * kvs[l][dd];
            a1 += qd * kvs[l + 32][dd];
        }
        size_t o = (size_t)(b * PM + m) * PC + h * DC;
        out[o + l]      = z * a0;
        out[o + l + 32] = z * a1;
    }
}

// ---------------------------------------------------------------------
extern "C" void kernel_launch(void* const* d_in, const int* in_sizes, int n_in,
                              void* d_out, int out_size)
{
    const float* input = (const float*)d_in[0];  // [B,N,C]
    const float* query = (const float*)d_in[1];  // [B,M,C]
    const float* Wq    = (const float*)d_in[2];  // [C,L]
    const float* bq    = (const float*)d_in[3];  // [L]
    const float* Wk    = (const float*)d_in[4];  // [C,L]
    const float* bk    = (const float*)d_in[5];  // [L]
    const float* Wv    = (const float*)d_in[6];  // [C,C]
    const float* bv    = (const float*)d_in[7];  // [C]
    float* out = (float*)d_out;
    (void)in_sizes; (void)n_in; (void)out_size;

    cudaFuncSetAttribute(gemm_mma_kernel,
                         cudaFuncAttributeMaxDynamicSharedMemorySize, SMEM_BYTES);

    // 1) zero kv/ksum accumulators
    int nacc = PB * PH * DC * DL + PB * PH * DL;
    zero_kernel<<<(nacc + 255) / 256, 256>>>(nacc);

    // 2) transpose weights into g_wt (K-major rows, tf32-rounded)
    const int OFF_K = 0;
    const int OFF_V = PL * PC;
    const int OFF_Q = PL * PC + PC * PC;
    transpose_kernel<<<dim3(PL / 32, PC / 32), dim3(32, 8)>>>(Wk, PL, OFF_K);
    transpose_kernel<<<dim3(PC / 32, PC / 32), dim3(32, 8)>>>(Wv, PC, OFF_V);
    transpose_kernel<<<dim3(PL / 32, PC / 32), dim3(32, 8)>>>(Wq, PL, OFF_Q);

    // 3) projections on tensor cores (tf32 mma.sync)
    gemm_mma_kernel<<<dim3(PL / TN, (PB * PN) / TM), 256, SMEM_BYTES>>>(
        input, OFF_K, bk, PL, 1, 0);   // k = elu(X@Wk+bk)+1
    gemm_mma_kernel<<<dim3(PC / TN, (PB * PN) / TM), 256, SMEM_BYTES>>>(
        input, OFF_V, bv, PC, 0, 1);   // v = X@Wv+bv
    gemm_mma_kernel<<<dim3(PL / TN, (PB * PM) / TM), 256, SMEM_BYTES>>>(
        query, OFF_Q, bq, PL, 1, 2);   // q = elu(Q@Wq+bq)+1

    // 4) kv / ksum accumulation
    kv_accum_kernel<<<PB * PH * NCHUNK, 256>>>();

    // 5) output
    out_kernel<<<dim3(PB * PH, PM / 64), 256>>>(out);
}

// round 4
// speedup vs baseline: 2.6435x; 1.1039x over previous
#include <cuda_runtime.h>
#include <cstdint>
#include <math.h>

// Problem constants (LinearAttention_22943715295778)
#define PB 4
#define PN 8192
#define PM 2048
#define PC 512
#define PL 256
#define PH 8
#define DL 32   // L/H
#define DC 64   // C/H
#define EPS 1e-6f

#define NKV 768                                   // k cols (256) + v cols (512)
#define NACC (PB*PH*DC*DL + PB*PH*DL)             // 66560

// -------- device-global scratch (allocation-free requirement) --------
__device__ float g_kvbuf[PB * PN * NKV];          // 96 MB : [k | v] projections
__device__ float g_acc[NACC];                     // kv (65536) + ksum (1024)
__device__ float g_wt[1024 * PC];                 // rows: [WkT 256][WvT 512][WqT 256], tf32
__device__ float g_bias[1024];                    // [bk | bv | bq]

// ===================== helpers =====================
__device__ __forceinline__ uint32_t smem_u32(const void* p) {
    uint32_t a;
    asm("{ .reg .u64 t; cvta.to.shared.u64 t, %1; cvt.u32.u64 %0, t; }"
        : "=r"(a) : "l"(p));
    return a;
}
__device__ __forceinline__ uint32_t tf32r(float x) {  // round-to-nearest tf32
    uint32_t y;
    asm("cvt.rna.tf32.f32 %0, %1;" : "=r"(y) : "f"(x));
    return y;
}

// ===================== prep: transposes + bias + zero =====================
// grid (32,16), block (32,8). bx -> 32 wt rows, by -> 32 k's.
__global__ __launch_bounds__(256) void prep_kernel(
    const float* __restrict__ Wk, const float* __restrict__ Wv,
    const float* __restrict__ Wq,
    const float* __restrict__ bk, const float* __restrict__ bv,
    const float* __restrict__ bq)
{
    __shared__ float tile[32][33];
    const int n0 = blockIdx.x * 32, k0 = blockIdx.y * 32;
    const float *W, *bsrc; int N, ns;
    if (n0 < 256)      { W = Wk; bsrc = bk; N = PL; ns = n0; }
    else if (n0 < 768) { W = Wv; bsrc = bv; N = PC; ns = n0 - 256; }
    else               { W = Wq; bsrc = bq; N = PL; ns = n0 - 768; }
    const int tx = threadIdx.x, ty = threadIdx.y;
    for (int i = ty; i < 32; i += 8)
        tile[i][tx] = W[(size_t)(k0 + i) * N + ns + tx];
    __syncthreads();
    for (int i = ty; i < 32; i += 8)
        g_wt[(size_t)(n0 + i) * PC + k0 + tx] = __uint_as_float(tf32r(tile[tx][i]));
    if (blockIdx.y == 0 && ty == 0)
        g_bias[n0 + tx] = bsrc[ns + tx];
    if (blockIdx.y == 1) {
        int t = ty * 32 + tx;
#pragma unroll
        for (int i = 0; i < 9; i++) {
            int j = blockIdx.x * 256 + t + i * 8192;
            if (j < NACC) g_acc[j] = 0.0f;
        }
    }
}

// ===================== shared tf32 mma mainloop =====================
// CTA tile 128x128, BK=32, 2-stage cp.async. 8 warps (4M x 2N), warp 32x64.
// Fragment loads are float2 via the consistent k-permutation (memory cols
// kk+2lc, kk+2lc+1 interpreted as mma-k lc, lc+4 on BOTH operands).
#define TMm 128
#define TNn 128
#define BKk 32
#define KPAD 40
#define NCHh 16
#define SMEM_GEMM (4 * 4 * TMm * KPAD)            // 81920 bytes

__device__ __forceinline__ void mma_tile_loop(
    const float* __restrict__ Ag0,   // A + row0*512 (row stride 512)
    const float* __restrict__ Bg0,   // g_wt + wtrow0*512
    float* sm, int t, float acc[2][8][4])
{
    float* As = sm;                     // [2][128][KPAD]
    float* Bs = sm + 2 * TMm * KPAD;    // [2][128][KPAD]
    const int wid = t >> 5, lane = t & 31;
    const int lr = lane >> 2, lc = lane & 3;
    const int wm = (wid & 3) * 32, wn = (wid >> 2) * 64;

    auto stage = [&](int c, int buf) {
        const float* Ag = Ag0 + c * BKk;
        const float* Bg = Bg0 + c * BKk;
        float* Ad = As + buf * TMm * KPAD;
        float* Bd = Bs + buf * TNn * KPAD;
#pragma unroll
        for (int i = 0; i < 4; i++) {
            int idx = i * 256 + t;          // 0..1023
            int r = idx >> 3, c4 = idx & 7;
            asm volatile("cp.async.cg.shared.global [%0], [%1], 16;"
                :: "r"(smem_u32(Ad + r * KPAD + c4 * 4)),
                   "l"(Ag + (size_t)r * PC + c4 * 4));
            asm volatile("cp.async.cg.shared.global [%0], [%1], 16;"
                :: "r"(smem_u32(Bd + r * KPAD + c4 * 4)),
                   "l"(Bg + (size_t)r * PC + c4 * 4));
        }
        asm volatile("cp.async.commit_group;" ::: "memory");
    };

    auto compute = [&](int buf) {
        const float* Ab = As + buf * TMm * KPAD;
        const float* Bb = Bs + buf * TNn * KPAD;
#pragma unroll
        for (int kk = 0; kk < BKk; kk += 8) {
            uint32_t af[2][4], bf[8][2];
#pragma unroll
            for (int mi = 0; mi < 2; mi++) {
                float2 r0 = *(const float2*)&Ab[(wm + mi * 16 + lr) * KPAD + kk + 2 * lc];
                float2 r1 = *(const float2*)&Ab[(wm + mi * 16 + lr + 8) * KPAD + kk + 2 * lc];
                af[mi][0] = tf32r(r0.x); af[mi][1] = tf32r(r1.x);
                af[mi][2] = tf32r(r0.y); af[mi][3] = tf32r(r1.y);
            }
#pragma unroll
            for (int ni = 0; ni < 8; ni++) {
                float2 v = *(const float2*)&Bb[(wn + ni * 8 + lr) * KPAD + kk + 2 * lc];
                bf[ni][0] = __float_as_uint(v.x);
                bf[ni][1] = __float_as_uint(v.y);
            }
#pragma unroll
            for (int mi = 0; mi < 2; mi++)
#pragma unroll
                for (int ni = 0; ni < 8; ni++)
                    asm volatile(
                        "mma.sync.aligned.m16n8k8.row.col.f32.tf32.tf32.f32 "
                        "{%0,%1,%2,%3}, {%4,%5,%6,%7}, {%8,%9}, {%0,%1,%2,%3};"
                        : "+f"(acc[mi][ni][0]), "+f"(acc[mi][ni][1]),
                          "+f"(acc[mi][ni][2]), "+f"(acc[mi][ni][3])
                        : "r"(af[mi][0]), "r"(af[mi][1]),
                          "r"(af[mi][2]), "r"(af[mi][3]),
                          "r"(bf[ni][0]), "r"(bf[ni][1]));
        }
    };

    stage(0, 0);
    for (int c = 0; c < NCHh; c++) {
        if (c + 1 < NCHh) {
            stage(c + 1, (c + 1) & 1);
            asm volatile("cp.async.wait_group 1;" ::: "memory");
        } else {
            asm volatile("cp.async.wait_group 0;" ::: "memory");
        }
        __syncthreads();
        compute(c & 1);
        __syncthreads();
    }
}

// ===================== combined k|v projection GEMM =====================
// grid (6, 256): col0 in [0,768), row0 in [0,32768). elu iff col0 < 256.
__global__ __launch_bounds__(256, 2) void kv_gemm_kernel(const float* __restrict__ A)
{
    extern __shared__ float sm[];
    const int t = threadIdx.x;
    const int row0 = blockIdx.y * TMm;
    const int col0 = blockIdx.x * TNn;

    float acc[2][8][4];
#pragma unroll
    for (int mi = 0; mi < 2; mi++)
#pragma unroll
        for (int ni = 0; ni < 8; ni++)
#pragma unroll
            for (int j = 0; j < 4; j++) acc[mi][ni][j] = 0.0f;

    mma_tile_loop(A + (size_t)row0 * PC, g_wt + (size_t)col0 * PC, sm, t, acc);

    const int wid = t >> 5, lane = t & 31, lr = lane >> 2, lc = lane & 3;
    const int wm = (wid & 3) * 32, wn = (wid >> 2) * 64;
    const bool elu = (col0 < 256);
#pragma unroll
    for (int mi = 0; mi < 2; mi++)
#pragma unroll
        for (int ni = 0; ni < 8; ni++) {
            int r  = row0 + wm + mi * 16 + lr;
            int cc = col0 + wn + ni * 8 + 2 * lc;
            float b0 = g_bias[cc], b1 = g_bias[cc + 1];
            float x0 = acc[mi][ni][0] + b0;
            float x1 = acc[mi][ni][1] + b1;
            float x2 = acc[mi][ni][2] + b0;
            float x3 = acc[mi][ni][3] + b1;
            if (elu) {
                x0 = x0 > 0.0f ? x0 + 1.0f : expf(x0);
                x1 = x1 > 0.0f ? x1 + 1.0f : expf(x1);
                x2 = x2 > 0.0f ? x2 + 1.0f : expf(x2);
                x3 = x3 > 0.0f ? x3 + 1.0f : expf(x3);
            }
            float2 s0 = {x0, x1}, s1 = {x2, x3};
            *(float2*)&g_kvbuf[(size_t)r * NKV + cc]       = s0;
            *(float2*)&g_kvbuf[(size_t)(r + 8) * NKV + cc] = s1;
        }
}

// ---------------------------------------------------------------------
// kv[b,h,c,d] = sum_n k[b,n,h,d] * v[b,n,h,c];  ksum[b,h,d] = sum_n k
// ---------------------------------------------------------------------
#define NCHUNK 16

__global__ __launch_bounds__(256) void kv_accum_kernel()
{
    const int bid   = blockIdx.x;
    const int chunk = bid % NCHUNK;
    const int bh    = bid / NCHUNK;
    const int h     = bh % PH;
    const int b     = bh / PH;
    const int n0    = chunk * (PN / NCHUNK);

    __shared__ float ks[64][32];
    __shared__ float vs[64][64];

    const int t  = threadIdx.x;
    const int d  = t & 31;
    const int cb = (t >> 5) * 8;

    float acc[8];
#pragma unroll
    for (int j = 0; j < 8; j++) acc[j] = 0.0f;
    float ksacc = 0.0f;

    for (int nt = 0; nt < PN / NCHUNK; nt += 64) {
#pragma unroll
        for (int i = 0; i < 8; i++) {
            int flat = t + i * 256;
            int nl = flat >> 5, dd = flat & 31;
            ks[nl][dd] = g_kvbuf[(size_t)(b * PN + n0 + nt + nl) * NKV + h * DL + dd];
        }
#pragma unroll
        for (int i = 0; i < 16; i++) {
            int flat = t + i * 256;
            int nl = flat >> 6, cc = flat & 63;
            vs[nl][cc] = g_kvbuf[(size_t)(b * PN + n0 + nt + nl) * NKV + 256 + h * DC + cc];
        }
        __syncthreads();
#pragma unroll 4
        for (int nl = 0; nl < 64; nl++) {
            float kval = ks[nl][d];
            ksacc += kval;
#pragma unroll
            for (int j = 0; j < 8; j++)
                acc[j] += kval * vs[nl][cb + j];
        }
        __syncthreads();
    }

    float* kv   = g_acc;
    float* ksum = g_acc + PB * PH * DC * DL;
#pragma unroll
    for (int j = 0; j < 8; j++)
        atomicAdd(&kv[((size_t)bh * DC + cb + j) * DL + d], acc[j]);
    if (t < 32)
        atomicAdd(&ksum[bh * DL + t], ksacc);
}

// ===================== fused q-projection + output =====================
// grid (2, 64). Computes q-tile 128x128 (4 heads), keeps it in smem, then
// out[b,m,h,c] = z * sum_d q*kv. Requires kv_accum done.
#define QS_STRIDE 132
#define SMEM_QOUT ((128 * QS_STRIDE + 4 * DC * DL + 4 * DL) * 4)  // 100864 B

__global__ __launch_bounds__(256, 1) void qout_kernel(
    const float* __restrict__ Q, float* __restrict__ out)
{
    extern __shared__ float sm[];
    const int t = threadIdx.x;
    const int row0 = blockIdx.y * TMm;   // global q row
    const int col0 = blockIdx.x * TNn;   // 0 or 128 (L cols)

    float acc[2][8][4];
#pragma unroll
    for (int mi = 0; mi < 2; mi++)
#pragma unroll
        for (int ni = 0; ni < 8; ni++)
#pragma unroll
            for (int j = 0; j < 4; j++) acc[mi][ni][j] = 0.0f;

    mma_tile_loop(Q + (size_t)row0 * PC, g_wt + (size_t)(768 + col0) * PC, sm, t, acc);
    // mma_tile_loop ends with __syncthreads(); smem now reusable.

    const int wid = t >> 5, lane = t & 31, lr = lane >> 2, lc = lane & 3;
    const int wm = (wid & 3) * 32, wn = (wid >> 2) * 64;

    float* qs  = sm;                          // [128][QS_STRIDE]
    float* kvs = sm + 128 * QS_STRIDE;        // [4][64][32]
    float* kss = kvs + 4 * DC * DL;           // [4][32]

#pragma unroll
    for (int mi = 0; mi < 2; mi++)
#pragma unroll
        for (int ni = 0; ni < 8; ni++) {
            int r  = wm + mi * 16 + lr;
            int cc = wn + ni * 8 + 2 * lc;
            float b0 = g_bias[768 + col0 + cc], b1 = g_bias[768 + col0 + cc + 1];
            float x0 = acc[mi][ni][0] + b0;
            float x1 = acc[mi][ni][1] + b1;
            float x2 = acc[mi][ni][2] + b0;
            float x3 = acc[mi][ni][3] + b1;
            x0 = x0 > 0.0f ? x0 + 1.0f : expf(x0);
            x1 = x1 > 0.0f ? x1 + 1.0f : expf(x1);
            x2 = x2 > 0.0f ? x2 + 1.0f : expf(x2);
            x3 = x3 > 0.0f ? x3 + 1.0f : expf(x3);
            float2 s0 = {x0, x1}, s1 = {x2, x3};
            *(float2*)&qs[r * QS_STRIDE + cc]       = s0;
            *(float2*)&qs[(r + 8) * QS_STRIDE + cc] = s1;
        }

    const int b  = row0 / PM;
    const int h0 = col0 / DL;                 // global head base (0 or 4)
    const float* kvg = g_acc + (size_t)(b * PH + h0) * DC * DL;
#pragma unroll
    for (int i = 0; i < 32; i++)              // 8192 floats
        kvs[t + i * 256] = kvg[t + i * 256];
    if (t < 128)
        kss[t] = g_acc[PB * PH * DC * DL + (b * PH + h0) * DL + t];
    __syncthreads();

    const int w  = t >> 5;
    const int hl = w & 3;
    const int hg = h0 + hl;
    const int rb = (w >> 2) * 64;
    const float* kvh = kvs + hl * DC * DL;
    const float* ksh = kss + hl * DL;

#pragma unroll
    for (int p = 0; p < 2; p++) {
        int m = rb + p * 32 + lane;
        const float4* qp = (const float4*)&qs[m * QS_STRIDE + hl * 32];
        float4 qv[8];
#pragma unroll
        for (int i = 0; i < 8; i++) qv[i] = qp[i];

        float zp = 0.0f;
#pragma unroll
        for (int i = 0; i < 8; i++) {
            float4 k4 = ((const float4*)ksh)[i];
            zp += qv[i].x * k4.x + qv[i].y * k4.y + qv[i].z * k4.z + qv[i].w * k4.w;
        }
        float z = 1.0f / (zp + EPS);

        size_t obase = (size_t)(row0 + m) * PC + hg * DC;
        for (int c4 = 0; c4 < 16; c4++) {
            float o[4];
#pragma unroll
            for (int cc = 0; cc < 4; cc++) {
                const float4* kp = (const float4*)&kvh[(c4 * 4 + cc) * DL];
                float s = 0.0f;
#pragma unroll
                for (int i = 0; i < 8; i++) {
                    float4 k4 = kp[i];
                    s += qv[i].x * k4.x + qv[i].y * k4.y +
                         qv[i].z * k4.z + qv[i].w * k4.w;
                }
                o[cc] = z * s;
            }
            float4 st = {o[0], o[1], o[2], o[3]};
            *(float4*)&out[obase + c4 * 4] = st;
        }
    }
}

// ---------------------------------------------------------------------
extern "C" void kernel_launch(void* const* d_in, const int* in_sizes, int n_in,
                              void* d_out, int out_size)
{
    const float* input = (const float*)d_in[0];  // [B,N,C]
    const float* query = (const float*)d_in[1];  // [B,M,C]
    const float* Wq    = (const float*)d_in[2];  // [C,L]
    const float* bq    = (const float*)d_in[3];  // [L]
    const float* Wk    = (const float*)d_in[4];  // [C,L]
    const float* bk    = (const float*)d_in[5];  // [L]
    const float* Wv    = (const float*)d_in[6];  // [C,C]
    const float* bv    = (const float*)d_in[7];  // [C]
    float* out = (float*)d_out;
    (void)in_sizes; (void)n_in; (void)out_size;

    cudaFuncSetAttribute(kv_gemm_kernel,
                         cudaFuncAttributeMaxDynamicSharedMemorySize, SMEM_GEMM);
    cudaFuncSetAttribute(qout_kernel,
                         cudaFuncAttributeMaxDynamicSharedMemorySize, SMEM_QOUT);

    // 1) prep: weight transposes (tf32-rounded) + bias gather + zero acc
    prep_kernel<<<dim3(32, 16), dim3(32, 8)>>>(Wk, Wv, Wq, bk, bv, bq);

    // 2) combined k|v projection GEMM
    kv_gemm_kernel<<<dim3(6, 256), 256, SMEM_GEMM>>>(input);

    // 3) kv / ksum accumulation
    kv_accum_kernel<<<PB * PH * NCHUNK, 256>>>();

    // 4) fused q projection + output
    qout_kernel<<<dim3(2, 64), 256, SMEM_QOUT>>>(query, out);
}

// round 5
// speedup vs baseline: 3.5597x; 1.3466x over previous
#include <cuda_runtime.h>
#include <cuda_fp16.h>
#include <cstdint>
#include <math.h>

// Problem constants (LinearAttention_22943715295778)
#define PB 4
#define PN 8192
#define PM 2048
#define PC 512
#define PL 256
#define PH 8
#define DL 32   // L/H
#define DC 64   // C/H
#define EPS 1e-6f

#define NKV 768                                   // k cols (256) + v cols (512)
#define NACC (PB*PH*DC*DL + PB*PH*DL)             // 66560

// -------- device-global scratch (allocation-free requirement) --------
__device__ float  g_kvbuf[PB * PN * NKV];         // 96 MB : [k | v] projections (fp32)
__device__ float  g_acc[NACC];                    // kv (65536) + ksum (1024)
__device__ __half g_xh[PB * PN * PC];             // 32 MB : input_tokens fp16
__device__ __half g_qh[PB * PM * PC];             //  8 MB : query_tokens fp16
__device__ __half g_wth[1024 * PC];               // rows: [WkT 256][WvT 512][WqT 256], fp16
__device__ float  g_bias[1024];                   // [bk | bv | bq]

// ===================== helpers =====================
__device__ __forceinline__ uint32_t smem_u32(const void* p) {
    uint32_t a;
    asm("{ .reg .u64 t; cvta.to.shared.u64 t, %1; cvt.u32.u64 %0, t; }"
        : "=r"(a) : "l"(p));
    return a;
}

// ===================== prep: weight transposes + bias + zero =====================
// grid (32,16), block (32,8). bx -> 32 wt rows, by -> 32 k's.
__global__ __launch_bounds__(256) void prep_kernel(
    const float* __restrict__ Wk, const float* __restrict__ Wv,
    const float* __restrict__ Wq,
    const float* __restrict__ bk, const float* __restrict__ bv,
    const float* __restrict__ bq)
{
    __shared__ float tile[32][33];
    const int n0 = blockIdx.x * 32, k0 = blockIdx.y * 32;
    const float *W, *bsrc; int N, ns;
    if (n0 < 256)      { W = Wk; bsrc = bk; N = PL; ns = n0; }
    else if (n0 < 768) { W = Wv; bsrc = bv; N = PC; ns = n0 - 256; }
    else               { W = Wq; bsrc = bq; N = PL; ns = n0 - 768; }
    const int tx = threadIdx.x, ty = threadIdx.y;
    for (int i = ty; i < 32; i += 8)
        tile[i][tx] = W[(size_t)(k0 + i) * N + ns + tx];
    __syncthreads();
    for (int i = ty; i < 32; i += 8)
        g_wth[(size_t)(n0 + i) * PC + k0 + tx] = __float2half_rn(tile[tx][i]);
    if (blockIdx.y == 0 && ty == 0)
        g_bias[n0 + tx] = bsrc[ns + tx];
    if (blockIdx.y == 1) {
        int t = ty * 32 + tx;
#pragma unroll
        for (int i = 0; i < 9; i++) {
            int j = blockIdx.x * 256 + t + i * 8192;
            if (j < NACC) g_acc[j] = 0.0f;
        }
    }
}

// ===================== fp16 conversion of X and Q =====================
__global__ __launch_bounds__(256) void convert_kernel(
    const float* __restrict__ X, const float* __restrict__ Q)
{
    const int nx = PB * PN * PC / 4;   // float4 count
    const int nq = PB * PM * PC / 4;
    int i = blockIdx.x * blockDim.x + threadIdx.x;
    if (i < nx) {
        float4 v = ((const float4*)X)[i];
        __half2* d = (__half2*)g_xh;
        d[2 * i]     = __floats2half2_rn(v.x, v.y);
        d[2 * i + 1] = __floats2half2_rn(v.z, v.w);
    } else if (i < nx + nq) {
        int j = i - nx;
        float4 v = ((const float4*)Q)[j];
        __half2* d = (__half2*)g_qh;
        d[2 * j]     = __floats2half2_rn(v.x, v.y);
        d[2 * j + 1] = __floats2half2_rn(v.z, v.w);
    }
}

// ===================== fp16 mma mainloop =====================
// CTA tile 128x128, BK=64 fp16, 2-stage cp.async. 8 warps (4M x 2N), warp 32x64.
// Row stride 80 fp16 (40 words, 160B): LDS.64 fragment loads conflict-free.
// Consistent k-permutation: memory k' = 16j+4lc+{0..3} == mma k {2lc,2lc+1,2lc+8,2lc+9}
// on BOTH operands, so each fragment pair is one 64-bit load.
#define TMm 128
#define TNn 128
#define BKh 64
#define SWORD 40                      // uint32 words per row
#define TILEW (128 * SWORD)           // 5120 words = 20480 B per tile
#define NCHh (PC / BKh)               // 8
#define SMEM_GEMM (4 * TILEW * 4)     // 81920 bytes

__device__ __forceinline__ void mma_tile_loop_h(
    const __half* __restrict__ Ag0,   // fp16 A base (row stride 512)
    const __half* __restrict__ Bg0,   // fp16 W^T base (row stride 512)
    uint32_t* sm, int t, float acc[2][8][4])
{
    uint32_t* As = sm;                  // [2][128][SWORD]
    uint32_t* Bs = sm + 2 * TILEW;
    const int wid = t >> 5, lane = t & 31;
    const int lr = lane >> 2, lc = lane & 3;
    const int wm = (wid & 3) * 32, wn = (wid >> 2) * 64;

    auto stage = [&](int c, int buf) {
        const __half* Ag = Ag0 + c * BKh;
        const __half* Bg = Bg0 + c * BKh;
        uint32_t* Ad = As + buf * TILEW;
        uint32_t* Bd = Bs + buf * TILEW;
#pragma unroll
        for (int i = 0; i < 4; i++) {
            int idx = i * 256 + t;          // 0..1023
            int r = idx >> 3, seg = idx & 7;
            asm volatile("cp.async.cg.shared.global [%0], [%1], 16;"
                :: "r"(smem_u32(Ad + r * SWORD + seg * 4)),
                   "l"(Ag + (size_t)r * PC + seg * 8));
            asm volatile("cp.async.cg.shared.global [%0], [%1], 16;"
                :: "r"(smem_u32(Bd + r * SWORD + seg * 4)),
                   "l"(Bg + (size_t)r * PC + seg * 8));
        }
        asm volatile("cp.async.commit_group;" ::: "memory");
    };

    auto compute = [&](int buf) {
        const uint32_t* Ab = As + buf * TILEW;
        const uint32_t* Bb = Bs + buf * TILEW;
#pragma unroll
        for (int j = 0; j < 4; j++) {      // 4 x k16 steps per 64-k chunk
            const int ko = 8 * j + 2 * lc;
            uint32_t af[2][4], bf[8][2];
#pragma unroll
            for (int mi = 0; mi < 2; mi++) {
                uint2 lo = *(const uint2*)&Ab[(wm + mi * 16 + lr) * SWORD + ko];
                uint2 hi = *(const uint2*)&Ab[(wm + mi * 16 + lr + 8) * SWORD + ko];
                af[mi][0] = lo.x; af[mi][1] = hi.x;
                af[mi][2] = lo.y; af[mi][3] = hi.y;
            }
#pragma unroll
            for (int ni = 0; ni < 8; ni++) {
                uint2 b = *(const uint2*)&Bb[(wn + ni * 8 + lr) * SWORD + ko];
                bf[ni][0] = b.x; bf[ni][1] = b.y;
            }
#pragma unroll
            for (int mi = 0; mi < 2; mi++)
#pragma unroll
                for (int ni = 0; ni < 8; ni++)
                    asm volatile(
                        "mma.sync.aligned.m16n8k16.row.col.f32.f16.f16.f32 "
                        "{%0,%1,%2,%3}, {%4,%5,%6,%7}, {%8,%9}, {%0,%1,%2,%3};"
                        : "+f"(acc[mi][ni][0]), "+f"(acc[mi][ni][1]),
                          "+f"(acc[mi][ni][2]), "+f"(acc[mi][ni][3])
                        : "r"(af[mi][0]), "r"(af[mi][1]),
                          "r"(af[mi][2]), "r"(af[mi][3]),
                          "r"(bf[ni][0]), "r"(bf[ni][1]));
        }
    };

    stage(0, 0);
    for (int c = 0; c < NCHh; c++) {
        if (c + 1 < NCHh) {
            stage(c + 1, (c + 1) & 1);
            asm volatile("cp.async.wait_group 1;" ::: "memory");
        } else {
            asm volatile("cp.async.wait_group 0;" ::: "memory");
        }
        __syncthreads();
        compute(c & 1);
        __syncthreads();
    }
}

// ===================== combined k|v projection GEMM =====================
// grid (6, 256): col0 in [0,768), row0 in [0,32768). elu iff col0 < 256.
__global__ __launch_bounds__(256, 2) void kv_gemm_kernel()
{
    extern __shared__ uint32_t smw[];
    const int t = threadIdx.x;
    const int row0 = blockIdx.y * TMm;
    const int col0 = blockIdx.x * TNn;

    float acc[2][8][4];
#pragma unroll
    for (int mi = 0; mi < 2; mi++)
#pragma unroll
        for (int ni = 0; ni < 8; ni++)
#pragma unroll
            for (int j = 0; j < 4; j++) acc[mi][ni][j] = 0.0f;

    mma_tile_loop_h(g_xh + (size_t)row0 * PC, g_wth + (size_t)col0 * PC, smw, t, acc);

    const int wid = t >> 5, lane = t & 31, lr = lane >> 2, lc = lane & 3;
    const int wm = (wid & 3) * 32, wn = (wid >> 2) * 64;
    const bool elu = (col0 < 256);
#pragma unroll
    for (int mi = 0; mi < 2; mi++)
#pragma unroll
        for (int ni = 0; ni < 8; ni++) {
            int r  = row0 + wm + mi * 16 + lr;
            int cc = col0 + wn + ni * 8 + 2 * lc;
            float b0 = g_bias[cc], b1 = g_bias[cc + 1];
            float x0 = acc[mi][ni][0] + b0;
            float x1 = acc[mi][ni][1] + b1;
            float x2 = acc[mi][ni][2] + b0;
            float x3 = acc[mi][ni][3] + b1;
            if (elu) {
                x0 = x0 > 0.0f ? x0 + 1.0f : expf(x0);
                x1 = x1 > 0.0f ? x1 + 1.0f : expf(x1);
                x2 = x2 > 0.0f ? x2 + 1.0f : expf(x2);
                x3 = x3 > 0.0f ? x3 + 1.0f : expf(x3);
            }
            float2 s0 = {x0, x1}, s1 = {x2, x3};
            *(float2*)&g_kvbuf[(size_t)r * NKV + cc]       = s0;
            *(float2*)&g_kvbuf[(size_t)(r + 8) * NKV + cc] = s1;
        }
}

// ---------------------------------------------------------------------
// kv[b,h,c,d] = sum_n k[b,n,h,d] * v[b,n,h,c];  ksum[b,h,d] = sum_n k
// ---------------------------------------------------------------------
#define NCHUNK 16

__global__ __launch_bounds__(256) void kv_accum_kernel()
{
    const int bid   = blockIdx.x;
    const int chunk = bid % NCHUNK;
    const int bh    = bid / NCHUNK;
    const int h     = bh % PH;
    const int b     = bh / PH;
    const int n0    = chunk * (PN / NCHUNK);

    __shared__ float ks[64][32];
    __shared__ float vs[64][64];

    const int t  = threadIdx.x;
    const int d  = t & 31;
    const int cb = (t >> 5) * 8;

    float acc[8];
#pragma unroll
    for (int j = 0; j < 8; j++) acc[j] = 0.0f;
    float ksacc = 0.0f;

    for (int nt = 0; nt < PN / NCHUNK; nt += 64) {
#pragma unroll
        for (int i = 0; i < 8; i++) {
            int flat = t + i * 256;
            int nl = flat >> 5, dd = flat & 31;
            ks[nl][dd] = g_kvbuf[(size_t)(b * PN + n0 + nt + nl) * NKV + h * DL + dd];
        }
#pragma unroll
        for (int i = 0; i < 16; i++) {
            int flat = t + i * 256;
            int nl = flat >> 6, cc = flat & 63;
            vs[nl][cc] = g_kvbuf[(size_t)(b * PN + n0 + nt + nl) * NKV + 256 + h * DC + cc];
        }
        __syncthreads();
#pragma unroll 4
        for (int nl = 0; nl < 64; nl++) {
            float kval = ks[nl][d];
            ksacc += kval;
#pragma unroll
            for (int j = 0; j < 8; j++)
                acc[j] += kval * vs[nl][cb + j];
        }
        __syncthreads();
    }

    float* kv   = g_acc;
    float* ksum = g_acc + PB * PH * DC * DL;
#pragma unroll
    for (int j = 0; j < 8; j++)
        atomicAdd(&kv[((size_t)bh * DC + cb + j) * DL + d], acc[j]);
    if (t < 32)
        atomicAdd(&ksum[bh * DL + t], ksacc);
}

// ===================== fused q-projection + output =====================
// grid (2, 64). Computes q-tile 128x128 (4 heads) in smem, then
// out[b,m,h,c] = z * sum_d q*kv. Requires kv_accum done.
#define QS_STRIDE 132
#define SMEM_QOUT ((128 * QS_STRIDE + 4 * DC * DL + 4 * DL) * 4)  // 100864 B

__global__ __launch_bounds__(256, 1) void qout_kernel(float* __restrict__ out)
{
    extern __shared__ uint32_t smw[];
    float* sm = (float*)smw;
    const int t = threadIdx.x;
    const int row0 = blockIdx.y * TMm;   // global q row
    const int col0 = blockIdx.x * TNn;   // 0 or 128 (L cols)

    float acc[2][8][4];
#pragma unroll
    for (int mi = 0; mi < 2; mi++)
#pragma unroll
        for (int ni = 0; ni < 8; ni++)
#pragma unroll
            for (int j = 0; j < 4; j++) acc[mi][ni][j] = 0.0f;

    mma_tile_loop_h(g_qh + (size_t)row0 * PC,
                    g_wth + (size_t)(768 + col0) * PC, smw, t, acc);
    // ends with __syncthreads(); smem reusable.

    const int wid = t >> 5, lane = t & 31, lr = lane >> 2, lc = lane & 3;
    const int wm = (wid & 3) * 32, wn = (wid >> 2) * 64;

    float* qs  = sm;                          // [128][QS_STRIDE]
    float* kvs = sm + 128 * QS_STRIDE;        // [4][64][32]
    float* kss = kvs + 4 * DC * DL;           // [4][32]

#pragma unroll
    for (int mi = 0; mi < 2; mi++)
#pragma unroll
        for (int ni = 0; ni < 8; ni++) {
            int r  = wm + mi * 16 + lr;
            int cc = wn + ni * 8 + 2 * lc;
            float b0 = g_bias[768 + col0 + cc], b1 = g_bias[768 + col0 + cc + 1];
            float x0 = acc[mi][ni][0] + b0;
            float x1 = acc[mi][ni][1] + b1;
            float x2 = acc[mi][ni][2] + b0;
            float x3 = acc[mi][ni][3] + b1;
            x0 = x0 > 0.0f ? x0 + 1.0f : expf(x0);
            x1 = x1 > 0.0f ? x1 + 1.0f : expf(x1);
            x2 = x2 > 0.0f ? x2 + 1.0f : expf(x2);
            x3 = x3 > 0.0f ? x3 + 1.0f : expf(x3);
            float2 s0 = {x0, x1}, s1 = {x2, x3};
            *(float2*)&qs[r * QS_STRIDE + cc]       = s0;
            *(float2*)&qs[(r + 8) * QS_STRIDE + cc] = s1;
        }

    const int b  = row0 / PM;
    const int h0 = col0 / DL;                 // global head base (0 or 4)
    const float* kvg = g_acc + (size_t)(b * PH + h0) * DC * DL;
#pragma unroll
    for (int i = 0; i < 32; i++)              // 8192 floats
        kvs[t + i * 256] = kvg[t + i * 256];
    if (t < 128)
        kss[t] = g_acc[PB * PH * DC * DL + (b * PH + h0) * DL + t];
    __syncthreads();

    const int w  = t >> 5;
    const int hl = w & 3;
    const int hg = h0 + hl;
    const int rb = (w >> 2) * 64;
    const float* kvh = kvs + hl * DC * DL;
    const float* ksh = kss + hl * DL;

#pragma unroll
    for (int p = 0; p < 2; p++) {
        int m = rb + p * 32 + lane;
        const float4* qp = (const float4*)&qs[m * QS_STRIDE + hl * 32];
        float4 qv[8];
#pragma unroll
        for (int i = 0; i < 8; i++) qv[i] = qp[i];

        float zp = 0.0f;
#pragma unroll
        for (int i = 0; i < 8; i++) {
            float4 k4 = ((const float4*)ksh)[i];
            zp += qv[i].x * k4.x + qv[i].y * k4.y + qv[i].z * k4.z + qv[i].w * k4.w;
        }
        float z = 1.0f / (zp + EPS);

        size_t obase = (size_t)(row0 + m) * PC + hg * DC;
        for (int c4 = 0; c4 < 16; c4++) {
            float o[4];
#pragma unroll
            for (int cc = 0; cc < 4; cc++) {
                const float4* kp = (const float4*)&kvh[(c4 * 4 + cc) * DL];
                float s = 0.0f;
#pragma unroll
                for (int i = 0; i < 8; i++) {
                    float4 k4 = kp[i];
                    s += qv[i].x * k4.x + qv[i].y * k4.y +
                         qv[i].z * k4.z + qv[i].w * k4.w;
                }
                o[cc] = z * s;
            }
            float4 st = {o[0], o[1], o[2], o[3]};
            *(float4*)&out[obase + c4 * 4] = st;
        }
    }
}

// ---------------------------------------------------------------------
extern "C" void kernel_launch(void* const* d_in, const int* in_sizes, int n_in,
                              void* d_out, int out_size)
{
    const float* input = (const float*)d_in[0];  // [B,N,C]
    const float* query = (const float*)d_in[1];  // [B,M,C]
    const float* Wq    = (const float*)d_in[2];  // [C,L]
    const float* bq    = (const float*)d_in[3];  // [L]
    const float* Wk    = (const float*)d_in[4];  // [C,L]
    const float* bk    = (const float*)d_in[5];  // [L]
    const float* Wv    = (const float*)d_in[6];  // [C,C]
    const float* bv    = (const float*)d_in[7];  // [C]
    float* out = (float*)d_out;
    (void)in_sizes; (void)n_in; (void)out_size;

    cudaFuncSetAttribute(kv_gemm_kernel,
                         cudaFuncAttributeMaxDynamicSharedMemorySize, SMEM_GEMM);
    cudaFuncSetAttribute(qout_kernel,
                         cudaFuncAttributeMaxDynamicSharedMemorySize, SMEM_QOUT);

    // 1) prep: weight transposes (fp16) + bias gather + zero acc
    prep_kernel<<<dim3(32, 16), dim3(32, 8)>>>(Wk, Wv, Wq, bk, bv, bq);

    // 2) convert X and Q to fp16
    const int ncv = (PB * PN * PC + PB * PM * PC) / 4;
    convert_kernel<<<(ncv + 255) / 256, 256>>>(input, query);

    // 3) combined k|v projection GEMM (fp16 tensor cores)
    kv_gemm_kernel<<<dim3(6, 256), 256, SMEM_GEMM>>>();

    // 4) kv / ksum accumulation
    kv_accum_kernel<<<PB * PH * NCHUNK, 256>>>();

    // 5) fused q projection + output
    qout_kernel<<<dim3(2, 64), 256, SMEM_QOUT>>>(out);
}

// round 6
// speedup vs baseline: 4.8463x; 1.3614x over previous
#include <cuda_runtime.h>
#include <cuda_fp16.h>
#include <cstdint>
#include <math.h>

// Problem constants (LinearAttention_22943715295778)
#define PB 4
#define PN 8192
#define PM 2048
#define PC 512
#define PL 256
#define PH 8
#define DL 32   // L/H
#define DC 64   // C/H
#define EPS 1e-6f

#define NACC (PB*PH*DC*DL + PB*PH*DL)             // 66560

// -------- device-global scratch (allocation-free requirement) --------
__device__ __half g_kt[PB * PH * DL * PN];        // 16 MB : k^T [bh][d][n], fp16, post-elu
__device__ __half g_vt[PB * PH * DC * PN];        // 32 MB : v^T [bh][c][n], fp16
__device__ float  g_acc[NACC];                    // kv (65536) + ksum (1024)
__device__ __half g_xh[PB * PN * PC];             // 32 MB : input_tokens fp16
__device__ __half g_qh[PB * PM * PC];             //  8 MB : query_tokens fp16
__device__ __half g_wth[1024 * PC];               // rows: [WkT 256][WvT 512][WqT 256], fp16
__device__ float  g_bias[1024];                   // [bk | bv | bq]

// ===================== helpers =====================
__device__ __forceinline__ uint32_t smem_u32(const void* p) {
    uint32_t a;
    asm("{ .reg .u64 t; cvta.to.shared.u64 t, %1; cvt.u32.u64 %0, t; }"
        : "=r"(a) : "l"(p));
    return a;
}

// ===================== prep: weight transposes + bias + zero =====================
__global__ __launch_bounds__(256) void prep_kernel(
    const float* __restrict__ Wk, const float* __restrict__ Wv,
    const float* __restrict__ Wq,
    const float* __restrict__ bk, const float* __restrict__ bv,
    const float* __restrict__ bq)
{
    __shared__ float tile[32][33];
    const int n0 = blockIdx.x * 32, k0 = blockIdx.y * 32;
    const float *W, *bsrc; int N, ns;
    if (n0 < 256)      { W = Wk; bsrc = bk; N = PL; ns = n0; }
    else if (n0 < 768) { W = Wv; bsrc = bv; N = PC; ns = n0 - 256; }
    else               { W = Wq; bsrc = bq; N = PL; ns = n0 - 768; }
    const int tx = threadIdx.x, ty = threadIdx.y;
    for (int i = ty; i < 32; i += 8)
        tile[i][tx] = W[(size_t)(k0 + i) * N + ns + tx];
    __syncthreads();
    for (int i = ty; i < 32; i += 8)
        g_wth[(size_t)(n0 + i) * PC + k0 + tx] = __float2half_rn(tile[tx][i]);
    if (blockIdx.y == 0 && ty == 0)
        g_bias[n0 + tx] = bsrc[ns + tx];
    if (blockIdx.y == 1) {
        int t = ty * 32 + tx;
#pragma unroll
        for (int i = 0; i < 9; i++) {
            int j = blockIdx.x * 256 + t + i * 8192;
            if (j < NACC) g_acc[j] = 0.0f;
        }
    }
}

// ===================== fp16 conversion of X and Q =====================
__global__ __launch_bounds__(256) void convert_kernel(
    const float* __restrict__ X, const float* __restrict__ Q)
{
    const int nx = PB * PN * PC / 4;   // float4 count
    const int nq = PB * PM * PC / 4;
    int i = blockIdx.x * blockDim.x + threadIdx.x;
    if (i < nx) {
        float4 v = ((const float4*)X)[i];
        __half2* d = (__half2*)g_xh;
        d[2 * i]     = __floats2half2_rn(v.x, v.y);
        d[2 * i + 1] = __floats2half2_rn(v.z, v.w);
    } else if (i < nx + nq) {
        int j = i - nx;
        float4 v = ((const float4*)Q)[j];
        __half2* d = (__half2*)g_qh;
        d[2 * j]     = __floats2half2_rn(v.x, v.y);
        d[2 * j + 1] = __floats2half2_rn(v.z, v.w);
    }
}

// ===================== fp16 mma mainloop (shared) =====================
// CTA tile 128x128, BK=64 fp16, 2-stage cp.async. 8 warps (4M x 2N), warp 32x64.
// Consistent k-permutation: 64-bit fragment loads on both operands.
#define TMm 128
#define TNn 128
#define BKh 64
#define SWORD 40                      // uint32 words per row (64 fp16 + pad)
#define TILEW (128 * SWORD)
#define NCHh (PC / BKh)               // 8
#define SMEM_GEMM (4 * TILEW * 4)     // 81920 bytes

__device__ __forceinline__ void mma_tile_loop_h(
    const __half* __restrict__ Ag0,
    const __half* __restrict__ Bg0,
    uint32_t* sm, int t, float acc[2][8][4])
{
    uint32_t* As = sm;
    uint32_t* Bs = sm + 2 * TILEW;
    const int wid = t >> 5, lane = t & 31;
    const int lr = lane >> 2, lc = lane & 3;
    const int wm = (wid & 3) * 32, wn = (wid >> 2) * 64;

    auto stage = [&](int c, int buf) {
        const __half* Ag = Ag0 + c * BKh;
        const __half* Bg = Bg0 + c * BKh;
        uint32_t* Ad = As + buf * TILEW;
        uint32_t* Bd = Bs + buf * TILEW;
#pragma unroll
        for (int i = 0; i < 4; i++) {
            int idx = i * 256 + t;
            int r = idx >> 3, seg = idx & 7;
            asm volatile("cp.async.cg.shared.global [%0], [%1], 16;"
                :: "r"(smem_u32(Ad + r * SWORD + seg * 4)),
                   "l"(Ag + (size_t)r * PC + seg * 8));
            asm volatile("cp.async.cg.shared.global [%0], [%1], 16;"
                :: "r"(smem_u32(Bd + r * SWORD + seg * 4)),
                   "l"(Bg + (size_t)r * PC + seg * 8));
        }
        asm volatile("cp.async.commit_group;" ::: "memory");
    };

    auto compute = [&](int buf) {
        const uint32_t* Ab = As + buf * TILEW;
        const uint32_t* Bb = Bs + buf * TILEW;
#pragma unroll
        for (int j = 0; j < 4; j++) {
            const int ko = 8 * j + 2 * lc;
            uint32_t af[2][4], bf[8][2];
#pragma unroll
            for (int mi = 0; mi < 2; mi++) {
                uint2 lo = *(const uint2*)&Ab[(wm + mi * 16 + lr) * SWORD + ko];
                uint2 hi = *(const uint2*)&Ab[(wm + mi * 16 + lr + 8) * SWORD + ko];
                af[mi][0] = lo.x; af[mi][1] = hi.x;
                af[mi][2] = lo.y; af[mi][3] = hi.y;
            }
#pragma unroll
            for (int ni = 0; ni < 8; ni++) {
                uint2 b = *(const uint2*)&Bb[(wn + ni * 8 + lr) * SWORD + ko];
                bf[ni][0] = b.x; bf[ni][1] = b.y;
            }
#pragma unroll
            for (int mi = 0; mi < 2; mi++)
#pragma unroll
                for (int ni = 0; ni < 8; ni++)
                    asm volatile(
                        "mma.sync.aligned.m16n8k16.row.col.f32.f16.f16.f32 "
                        "{%0,%1,%2,%3}, {%4,%5,%6,%7}, {%8,%9}, {%0,%1,%2,%3};"
                        : "+f"(acc[mi][ni][0]), "+f"(acc[mi][ni][1]),
                          "+f"(acc[mi][ni][2]), "+f"(acc[mi][ni][3])
                        : "r"(af[mi][0]), "r"(af[mi][1]),
                          "r"(af[mi][2]), "r"(af[mi][3]),
                          "r"(bf[ni][0]), "r"(bf[ni][1]));
        }
    };

    stage(0, 0);
    for (int c = 0; c < NCHh; c++) {
        if (c + 1 < NCHh) {
            stage(c + 1, (c + 1) & 1);
            asm volatile("cp.async.wait_group 1;" ::: "memory");
        } else {
            asm volatile("cp.async.wait_group 0;" ::: "memory");
        }
        __syncthreads();
        compute(c & 1);
        __syncthreads();
    }
}

// ===================== combined k|v projection GEMM =====================
// grid (6, 256). Writes fp16 TRANSPOSED outputs: k^T and v^T (via smem).
#define TSTR 136   // fp16 stride of transpose buffer rows

__global__ __launch_bounds__(256, 2) void kv_gemm_kernel()
{
    extern __shared__ uint32_t smw[];
    const int t = threadIdx.x;
    const int row0 = blockIdx.y * TMm;
    const int col0 = blockIdx.x * TNn;

    float acc[2][8][4];
#pragma unroll
    for (int mi = 0; mi < 2; mi++)
#pragma unroll
        for (int ni = 0; ni < 8; ni++)
#pragma unroll
            for (int j = 0; j < 4; j++) acc[mi][ni][j] = 0.0f;

    mma_tile_loop_h(g_xh + (size_t)row0 * PC, g_wth + (size_t)col0 * PC, smw, t, acc);
    // ends with __syncthreads(); smem reusable.

    const int wid = t >> 5, lane = t & 31, lr = lane >> 2, lc = lane & 3;
    const int wm = (wid & 3) * 32, wn = (wid >> 2) * 64;
    const bool elu = (col0 < 256);

    __half* st = (__half*)smw;   // [128 cols][TSTR]
#pragma unroll
    for (int mi = 0; mi < 2; mi++)
#pragma unroll
        for (int ni = 0; ni < 8; ni++) {
            int r  = wm + mi * 16 + lr;
            int cc = wn + ni * 8 + 2 * lc;
            float b0 = g_bias[col0 + cc], b1 = g_bias[col0 + cc + 1];
            float x0 = acc[mi][ni][0] + b0;
            float x1 = acc[mi][ni][1] + b1;
            float x2 = acc[mi][ni][2] + b0;
            float x3 = acc[mi][ni][3] + b1;
            if (elu) {
                x0 = x0 > 0.0f ? x0 + 1.0f : expf(x0);
                x1 = x1 > 0.0f ? x1 + 1.0f : expf(x1);
                x2 = x2 > 0.0f ? x2 + 1.0f : expf(x2);
                x3 = x3 > 0.0f ? x3 + 1.0f : expf(x3);
            }
            st[cc * TSTR + r]           = __float2half_rn(x0);
            st[(cc + 1) * TSTR + r]     = __float2half_rn(x1);
            st[cc * TSTR + r + 8]       = __float2half_rn(x2);
            st[(cc + 1) * TSTR + r + 8] = __float2half_rn(x3);
        }
    __syncthreads();

    const int b  = row0 >> 13;        // /8192
    const int n0 = row0 & 8191;
#pragma unroll
    for (int i = 0; i < 8; i++) {
        int flat = t + i * 256;
        int col = flat >> 4, seg = flat & 15;
        uint4 val = *(const uint4*)&st[col * TSTR + seg * 8];
        int g = col0 + col;
        __half* dst;
        if (g < 256) {        // k^T [bh][d][n]
            dst = g_kt + ((size_t)((b * PH + (g >> 5)) * DL + (g & 31))) * PN + n0 + seg * 8;
        } else {              // v^T [bh][c][n]
            int gv = g - 256;
            dst = g_vt + ((size_t)((b * PH + (gv >> 6)) * DC + (gv & 63))) * PN + n0 + seg * 8;
        }
        *(uint4*)dst = val;
    }
}

// ===================== kv aggregation via tensor cores =====================
// Per (b,h): kv[c,d] = sum_n v^T[c][n] * k^T[d][n]; ksum[d] = sum_n k^T[d][n].
// grid (32, 8 ksplits), 128 threads. M=64, N=32, K=1024 per CTA, fp32 atomics.
#define KA_BK 64
#define KA_AW (64 * SWORD)    // 2560 words
#define KA_BW (32 * SWORD)    // 1280 words

__global__ __launch_bounds__(128) void kv_accum_kernel()
{
    __shared__ uint32_t sbuf[2 * (KA_AW + KA_BW)];   // 30720 B

    const int bh = blockIdx.x;
    const int n0 = blockIdx.y * (PN / 8);
    const int t = threadIdx.x;
    const int w = t >> 5, lane = t & 31, lr = lane >> 2, lc = lane & 3;

    const __half* At = g_vt + (size_t)bh * DC * PN;   // rows c, stride PN
    const __half* Bt = g_kt + (size_t)bh * DL * PN;   // rows d, stride PN

    uint32_t* As = sbuf;
    uint32_t* Bs = sbuf + 2 * KA_AW;

    auto stage = [&](int c, int buf) {
        const __half* Ag = At + n0 + c * KA_BK;
        const __half* Bg = Bt + n0 + c * KA_BK;
        uint32_t* Ad = As + buf * KA_AW;
        uint32_t* Bd = Bs + buf * KA_BW;
#pragma unroll
        for (int i = 0; i < 4; i++) {             // A: 64 rows x 8 segs
            int idx = i * 128 + t;
            int r = idx >> 3, seg = idx & 7;
            asm volatile("cp.async.cg.shared.global [%0], [%1], 16;"
                :: "r"(smem_u32(Ad + r * SWORD + seg * 4)),
                   "l"(Ag + (size_t)r * PN + seg * 8));
        }
#pragma unroll
        for (int i = 0; i < 2; i++) {             // B: 32 rows x 8 segs
            int idx = i * 128 + t;
            int r = idx >> 3, seg = idx & 7;
            asm volatile("cp.async.cg.shared.global [%0], [%1], 16;"
                :: "r"(smem_u32(Bd + r * SWORD + seg * 4)),
                   "l"(Bg + (size_t)r * PN + seg * 8));
        }
        asm volatile("cp.async.commit_group;" ::: "memory");
    };

    float acc[4][4];
#pragma unroll
    for (int ni = 0; ni < 4; ni++)
#pragma unroll
        for (int j = 0; j < 4; j++) acc[ni][j] = 0.0f;
    float ksacc = 0.0f;

    auto compute = [&](int buf) {
        const uint32_t* Ab = As + buf * KA_AW;
        const uint32_t* Bb = Bs + buf * KA_BW;
#pragma unroll
        for (int j = 0; j < 4; j++) {
            const int ko = 8 * j + 2 * lc;
            uint32_t af[4];
            uint2 lo = *(const uint2*)&Ab[(16 * w + lr) * SWORD + ko];
            uint2 hi = *(const uint2*)&Ab[(16 * w + lr + 8) * SWORD + ko];
            af[0] = lo.x; af[1] = hi.x; af[2] = lo.y; af[3] = hi.y;
#pragma unroll
            for (int ni = 0; ni < 4; ni++) {
                uint2 b = *(const uint2*)&Bb[(ni * 8 + lr) * SWORD + ko];
                asm volatile(
                    "mma.sync.aligned.m16n8k16.row.col.f32.f16.f16.f32 "
                    "{%0,%1,%2,%3}, {%4,%5,%6,%7}, {%8,%9}, {%0,%1,%2,%3};"
                    : "+f"(acc[ni][0]), "+f"(acc[ni][1]),
                      "+f"(acc[ni][2]), "+f"(acc[ni][3])
                    : "r"(af[0]), "r"(af[1]), "r"(af[2]), "r"(af[3]),
                      "r"(b.x), "r"(b.y));
            }
        }
        // ksum partial: thread t sums 16 halves of k tile row d=(t>>2)
        const uint32_t* kp = Bb + (t >> 2) * SWORD + (t & 3) * 8;
#pragma unroll
        for (int i = 0; i < 8; i++) {
            float2 f = __half22float2(*(const __half2*)&kp[i]);
            ksacc += f.x + f.y;
        }
    };

    stage(0, 0);
    for (int c = 0; c < 16; c++) {
        if (c + 1 < 16) {
            stage(c + 1, (c + 1) & 1);
            asm volatile("cp.async.wait_group 1;" ::: "memory");
        } else {
            asm volatile("cp.async.wait_group 0;" ::: "memory");
        }
        __syncthreads();
        compute(c & 1);
        __syncthreads();
    }

    float* kv = g_acc;
#pragma unroll
    for (int ni = 0; ni < 4; ni++) {
        int d  = ni * 8 + 2 * lc;
        int c0 = 16 * w + lr;
        atomicAdd(&kv[((size_t)bh * DC + c0) * DL + d],         acc[ni][0]);
        atomicAdd(&kv[((size_t)bh * DC + c0) * DL + d + 1],     acc[ni][1]);
        atomicAdd(&kv[((size_t)bh * DC + c0 + 8) * DL + d],     acc[ni][2]);
        atomicAdd(&kv[((size_t)bh * DC + c0 + 8) * DL + d + 1], acc[ni][3]);
    }
    ksacc += __shfl_xor_sync(0xffffffffu, ksacc, 1);
    ksacc += __shfl_xor_sync(0xffffffffu, ksacc, 2);
    if ((t & 3) == 0)
        atomicAdd(&g_acc[PB * PH * DC * DL + bh * DL + (t >> 2)], ksacc);
}

// ===================== fused q-projection + output =====================
#define QS_STRIDE 132
#define SMEM_QOUT ((128 * QS_STRIDE + 4 * DC * DL + 4 * DL) * 4)  // 100864 B

__global__ __launch_bounds__(256, 1) void qout_kernel(float* __restrict__ out)
{
    extern __shared__ uint32_t smw[];
    float* sm = (float*)smw;
    const int t = threadIdx.x;
    const int row0 = blockIdx.y * TMm;
    const int col0 = blockIdx.x * TNn;

    float acc[2][8][4];
#pragma unroll
    for (int mi = 0; mi < 2; mi++)
#pragma unroll
        for (int ni = 0; ni < 8; ni++)
#pragma unroll
            for (int j = 0; j < 4; j++) acc[mi][ni][j] = 0.0f;

    mma_tile_loop_h(g_qh + (size_t)row0 * PC,
                    g_wth + (size_t)(768 + col0) * PC, smw, t, acc);

    const int wid = t >> 5, lane = t & 31, lr = lane >> 2, lc = lane & 3;
    const int wm = (wid & 3) * 32, wn = (wid >> 2) * 64;

    float* qs  = sm;                          // [128][QS_STRIDE]
    float* kvs = sm + 128 * QS_STRIDE;        // [4][64][32]
    float* kss = kvs + 4 * DC * DL;           // [4][32]

#pragma unroll
    for (int mi = 0; mi < 2; mi++)
#pragma unroll
        for (int ni = 0; ni < 8; ni++) {
            int r  = wm + mi * 16 + lr;
            int cc = wn + ni * 8 + 2 * lc;
            float b0 = g_bias[768 + col0 + cc], b1 = g_bias[768 + col0 + cc + 1];
            float x0 = acc[mi][ni][0] + b0;
            float x1 = acc[mi][ni][1] + b1;
            float x2 = acc[mi][ni][2] + b0;
            float x3 = acc[mi][ni][3] + b1;
            x0 = x0 > 0.0f ? x0 + 1.0f : expf(x0);
            x1 = x1 > 0.0f ? x1 + 1.0f : expf(x1);
            x2 = x2 > 0.0f ? x2 + 1.0f : expf(x2);
            x3 = x3 > 0.0f ? x3 + 1.0f : expf(x3);
            float2 s0 = {x0, x1}, s1 = {x2, x3};
            *(float2*)&qs[r * QS_STRIDE + cc]       = s0;
            *(float2*)&qs[(r + 8) * QS_STRIDE + cc] = s1;
        }

    const int b  = row0 / PM;
    const int h0 = col0 / DL;
    const float* kvg = g_acc + (size_t)(b * PH + h0) * DC * DL;
#pragma unroll
    for (int i = 0; i < 32; i++)
        kvs[t + i * 256] = kvg[t + i * 256];
    if (t < 128)
        kss[t] = g_acc[PB * PH * DC * DL + (b * PH + h0) * DL + t];
    __syncthreads();

    const int w  = t >> 5;
    const int hl = w & 3;
    const int hg = h0 + hl;
    const int rb = (w >> 2) * 64;
    const float* kvh = kvs + hl * DC * DL;
    const float* ksh = kss + hl * DL;

#pragma unroll
    for (int p = 0; p < 2; p++) {
        int m = rb + p * 32 + lane;
        const float4* qp = (const float4*)&qs[m * QS_STRIDE + hl * 32];
        float4 qv[8];
#pragma unroll
        for (int i = 0; i < 8; i++) qv[i] = qp[i];

        float zp = 0.0f;
#pragma unroll
        for (int i = 0; i < 8; i++) {
            float4 k4 = ((const float4*)ksh)[i];
            zp += qv[i].x * k4.x + qv[i].y * k4.y + qv[i].z * k4.z + qv[i].w * k4.w;
        }
        float z = 1.0f / (zp + EPS);

        size_t obase = (size_t)(row0 + m) * PC + hg * DC;
        for (int c4 = 0; c4 < 16; c4++) {
            float o[4];
#pragma unroll
            for (int cc = 0; cc < 4; cc++) {
                const float4* kp = (const float4*)&kvh[(c4 * 4 + cc) * DL];
                float s = 0.0f;
#pragma unroll
                for (int i = 0; i < 8; i++) {
                    float4 k4 = kp[i];
                    s += qv[i].x * k4.x + qv[i].y * k4.y +
                         qv[i].z * k4.z + qv[i].w * k4.w;
                }
                o[cc] = z * s;
            }
            float4 st = {o[0], o[1], o[2], o[3]};
            *(float4*)&out[obase + c4 * 4] = st;
        }
    }
}

// ---------------------------------------------------------------------
extern "C" void kernel_launch(void* const* d_in, const int* in_sizes, int n_in,
                              void* d_out, int out_size)
{
    const float* input = (const float*)d_in[0];
    const float* query = (const float*)d_in[1];
    const float* Wq    = (const float*)d_in[2];
    const float* bq    = (const float*)d_in[3];
    const float* Wk    = (const float*)d_in[4];
    const float* bk    = (const float*)d_in[5];
    const float* Wv    = (const float*)d_in[6];
    const float* bv    = (const float*)d_in[7];
    float* out = (float*)d_out;
    (void)in_sizes; (void)n_in; (void)out_size;

    cudaFuncSetAttribute(kv_gemm_kernel,
                         cudaFuncAttributeMaxDynamicSharedMemorySize, SMEM_GEMM);
    cudaFuncSetAttribute(qout_kernel,
                         cudaFuncAttributeMaxDynamicSharedMemorySize, SMEM_QOUT);

    // 1) prep: weight transposes (fp16) + bias gather + zero acc
    prep_kernel<<<dim3(32, 16), dim3(32, 8)>>>(Wk, Wv, Wq, bk, bv, bq);

    // 2) convert X and Q to fp16
    const int ncv = (PB * PN * PC + PB * PM * PC) / 4;
    convert_kernel<<<(ncv + 255) / 256, 256>>>(input, query);

    // 3) combined k|v projection GEMM -> transposed fp16 k^T / v^T
    kv_gemm_kernel<<<dim3(6, 256), 256, SMEM_GEMM>>>();

    // 4) kv / ksum aggregation on tensor cores
    kv_accum_kernel<<<dim3(32, 8), 128>>>();

    // 5) fused q projection + output
    qout_kernel<<<dim3(2, 64), 256, SMEM_QOUT>>>(out);
}